// round 5
// baseline (speedup 1.0000x reference)
#include <cuda_runtime.h>
#include <math.h>

#define B   16
#define C   512
#define T   1024
#define H   8
#define D   64

typedef unsigned long long ull;

// ---------------- scratch (static device, no allocation) ----------------
__device__ float g_q [B*H*T*D];   // [b,h,t,d]
__device__ float g_k [B*H*T*D];   // [b,h,t,d]
__device__ float g_v [B*H*T*D];   // [b,h,t,d]
__device__ float g_ao[B*C*T];     // [b,c,t]

// ---------------- packed fp32x2 helpers (sm_100+) ----------------
__device__ __forceinline__ ull pk2(float a, float b) {
    ull r; asm("mov.b64 %0, {%1,%2};" : "=l"(r) : "f"(a), "f"(b)); return r;
}
__device__ __forceinline__ void upk2(float& a, float& b, ull v) {
    asm("mov.b64 {%0,%1}, %2;" : "=f"(a), "=f"(b) : "l"(v));
}
#define FMA2(c, a, b) asm("fma.rn.f32x2 %0, %1, %2, %0;" : "+l"(c) : "l"(a), "l"(b))
#define MUL2(c, a)    asm("mul.rn.f32x2 %0, %0, %1;"     : "+l"(c) : "l"(a))

// =====================================================================
// Kernel 1: QKV projection.  out[b, o, t] = W[o,:] . x[b,:,t] + bias[o]
// Tile: 128 t  x 128 o  x  K-step 8.  256 threads, 8x8 per thread (f32x2).
// Writes q/k/v in [b,h,t,d] layout, coalesced (8 cols stay within one head).
// =====================================================================
__global__ __launch_bounds__(256) void qkv_gemm(
    const float* __restrict__ x,
    const float* __restrict__ Wq, const float* __restrict__ bq,
    const float* __restrict__ Wk, const float* __restrict__ bk,
    const float* __restrict__ Wv, const float* __restrict__ bv)
{
    __shared__ float As[8][132];  // x tile   [k][t]
    __shared__ float Bs[8][132];  // W^T tile [k][o]

    const int b  = blockIdx.z;
    const int w  = blockIdx.y >> 2;          // 0=q 1=k 2=v
    const int o0 = (blockIdx.y & 3) * 128;
    const int t0 = blockIdx.x * 128;

    const float* W    = (w == 0) ? Wq : (w == 1) ? Wk : Wv;
    const float* bias = (w == 0) ? bq : (w == 1) ? bk : bv;
    float*       outb = (w == 0) ? g_q : (w == 1) ? g_k : g_v;
    const float* Xb   = x + (size_t)b * C * T;

    const int tid = threadIdx.x;
    const int tx  = tid & 15, ty = tid >> 4;
    const int tm0 = ty * 8;          // t sub-tile
    const int tn0 = tx * 8;          // o sub-tile

    // load-index precompute
    const int la_k = tid >> 5;            // 0..7
    const int la_m = (tid & 31) * 4;      // 0..124
    const int lb_n = tid >> 1;            // 0..127
    const int lb_k = (tid & 1) * 4;       // 0 or 4

    ull acc[8][4];
    #pragma unroll
    for (int i = 0; i < 8; i++)
        #pragma unroll
        for (int j = 0; j < 4; j++) acc[i][j] = 0ull;

    for (int kk = 0; kk < C; kk += 8) {
        float4 av = *(const float4*)(Xb + (size_t)(kk + la_k) * T + t0 + la_m);
        float4 wv = *(const float4*)(W  + (size_t)(o0 + lb_n) * C + kk + lb_k);
        *(float4*)&As[la_k][la_m] = av;
        Bs[lb_k + 0][lb_n] = wv.x;
        Bs[lb_k + 1][lb_n] = wv.y;
        Bs[lb_k + 2][lb_n] = wv.z;
        Bs[lb_k + 3][lb_n] = wv.w;
        __syncthreads();
        #pragma unroll
        for (int k = 0; k < 8; k++) {
            float4 a0 = *(const float4*)&As[k][tm0];
            float4 a1 = *(const float4*)&As[k][tm0 + 4];
            const ull* bp = (const ull*)&Bs[k][tn0];
            ull bb0 = bp[0], bb1 = bp[1], bb2 = bp[2], bb3 = bp[3];
            float a[8] = {a0.x, a0.y, a0.z, a0.w, a1.x, a1.y, a1.z, a1.w};
            #pragma unroll
            for (int i = 0; i < 8; i++) {
                ull aa = pk2(a[i], a[i]);
                FMA2(acc[i][0], aa, bb0);
                FMA2(acc[i][1], aa, bb1);
                FMA2(acc[i][2], aa, bb2);
                FMA2(acc[i][3], aa, bb3);
            }
        }
        __syncthreads();
    }

    // epilogue: bias + write [b,h,t,d]
    const int oc = o0 + tn0;               // 8 consecutive channels, one head
    const int hh = oc >> 6, d0 = oc & 63;
    float bi[8];
    #pragma unroll
    for (int j = 0; j < 8; j++) bi[j] = bias[oc + j];
    float* obase = outb + ((size_t)(b * H + hh) * T) * D + d0;
    #pragma unroll
    for (int i = 0; i < 8; i++) {
        int t = t0 + tm0 + i;
        float r[8];
        #pragma unroll
        for (int jp = 0; jp < 4; jp++) upk2(r[2 * jp], r[2 * jp + 1], acc[i][jp]);
        float4 s0 = make_float4(r[0] + bi[0], r[1] + bi[1], r[2] + bi[2], r[3] + bi[3]);
        float4 s1 = make_float4(r[4] + bi[4], r[5] + bi[5], r[6] + bi[6], r[7] + bi[7]);
        *(float4*)(obase + (size_t)t * D)     = s0;
        *(float4*)(obase + (size_t)t * D + 4) = s1;
    }
}

// =====================================================================
// Kernel 2: RoPE in place on g_q and g_k (first 32 dims per head row).
// One thread per (buffer, row, i<16) rotation pair. Double-precision angles.
// =====================================================================
__global__ __launch_bounds__(256) void rope_kernel()
{
    const int idx = blockIdx.x * blockDim.x + threadIdx.x;   // 2 * 131072 * 16
    const int buf = idx >> 21;                // 2^21 = 131072*16 per buffer
    const int j   = idx & 2097151;
    const int row = j >> 4;                   // 0..131071  ([b,h,t] flattened)
    const int i   = j & 15;
    float* base   = (buf ? g_k : g_q) + (size_t)row * D;
    const int t   = row & (T - 1);

    // theta_i = 10000^(-i/16)
    double theta = exp(-(double)i * (9.210340371976184 / 16.0)); // ln(10000)
    double ang   = (double)t * theta;
    double cd, sd;
    sincos(ang, &sd, &cd);
    float c = (float)cd, s = (float)sd;

    float a = base[i];
    float bv = base[i + 16];
    base[i]      = a * c - bv * s;
    base[i + 16] = bv * c + a * s;
}

// =====================================================================
// Kernel 3: flash attention.  One block = (b, h, 64 q-rows).
// 256 threads (16x16), 4x4 per thread, online softmax, f32x2 math.
// K stored d-major in smem so key pairs are contiguous for f32x2.
// Output written [b,c,t] via smem transpose.
// =====================================================================
#define APAD 68    // row stride (floats): 16B-aligned, conflict-light

__global__ __launch_bounds__(256) void attn_kernel()
{
    extern __shared__ float sm[];
    float* Qs = sm;                 // [64][APAD]  row=q,   col=d   (pre-scaled)
    float* Kt = Qs + 64 * APAD;     // [64][APAD]  row=d,   col=key
    float* Vs = Kt + 64 * APAD;     // [64][APAD]  row=key, col=d
    float* Ss = Vs + 64 * APAD;     // [64][APAD]  row=q,   col=key / staging

    const int b  = blockIdx.z;
    const int h  = blockIdx.y;
    const int t0 = blockIdx.x * 64;
    const size_t bh = (size_t)(b * H + h);
    const float* Qg = g_q + bh * T * D;
    const float* Kg = g_k + bh * T * D;
    const float* Vg = g_v + bh * T * D;

    const int tid = threadIdx.x;
    const int tx  = tid & 15, ty = tid >> 4;

    // load Q (scaled by 1/sqrt(64) = 0.125)
    for (int i = tid; i < 64 * 16; i += 256) {
        int r = i >> 4, d4 = (i & 15) << 2;
        float4 qv = *(const float4*)(Qg + (size_t)(t0 + r) * D + d4);
        qv.x *= 0.125f; qv.y *= 0.125f; qv.z *= 0.125f; qv.w *= 0.125f;
        *(float4*)&Qs[r * APAD + d4] = qv;
    }

    ull o2[4][2];
    float mrow[4], lrow[4];
    #pragma unroll
    for (int i = 0; i < 4; i++) {
        o2[i][0] = 0ull; o2[i][1] = 0ull;
        mrow[i] = -INFINITY; lrow[i] = 0.0f;
    }

    for (int kb = 0; kb < T / 64; kb++) {
        const int k0 = kb * 64;
        // load K (transposed: d-major) and V
        for (int i = tid; i < 64 * 16; i += 256) {
            int r = i >> 4, d4 = (i & 15) << 2;
            float4 kv = *(const float4*)(Kg + (size_t)(k0 + r) * D + d4);
            Kt[(d4 + 0) * APAD + r] = kv.x;
            Kt[(d4 + 1) * APAD + r] = kv.y;
            Kt[(d4 + 2) * APAD + r] = kv.z;
            Kt[(d4 + 3) * APAD + r] = kv.w;
            float4 vv = *(const float4*)(Vg + (size_t)(k0 + r) * D + d4);
            *(float4*)&Vs[r * APAD + d4] = vv;
        }
        __syncthreads();   // also orders the Q-tile store on first iteration

        // S = Q K^T  (4 rows x 4 keys per thread, keys paired)
        ull s2[4][2];
        #pragma unroll
        for (int i = 0; i < 4; i++) { s2[i][0] = 0ull; s2[i][1] = 0ull; }
        #pragma unroll 8
        for (int d = 0; d < 64; d++) {
            ull kv0 = *(const ull*)&Kt[d * APAD + tx * 4];
            ull kv1 = *(const ull*)&Kt[d * APAD + tx * 4 + 2];
            #pragma unroll
            for (int i = 0; i < 4; i++) {
                float q = Qs[(ty * 4 + i) * APAD + d];
                ull qq = pk2(q, q);
                FMA2(s2[i][0], qq, kv0);
                FMA2(s2[i][1], qq, kv1);
            }
        }

        // online softmax (row groups = half-warps: lanes 0-15 / 16-31)
        #pragma unroll
        for (int i = 0; i < 4; i++) {
            float sa, sb, sc, sd;
            upk2(sa, sb, s2[i][0]);
            upk2(sc, sd, s2[i][1]);
            float mx = fmaxf(fmaxf(sa, sb), fmaxf(sc, sd));
            #pragma unroll
            for (int off = 8; off >= 1; off >>= 1)
                mx = fmaxf(mx, __shfl_xor_sync(0xffffffffu, mx, off));
            float mnew  = fmaxf(mrow[i], mx);
            float alpha = __expf(mrow[i] - mnew);
            float p0 = __expf(sa - mnew), p1 = __expf(sb - mnew);
            float p2 = __expf(sc - mnew), p3 = __expf(sd - mnew);
            float sum = p0 + p1 + p2 + p3;
            #pragma unroll
            for (int off = 8; off >= 1; off >>= 1)
                sum += __shfl_xor_sync(0xffffffffu, sum, off);
            lrow[i] = lrow[i] * alpha + sum;
            mrow[i] = mnew;
            ull a2 = pk2(alpha, alpha);
            MUL2(o2[i][0], a2);
            MUL2(o2[i][1], a2);
            int r = ty * 4 + i;
            Ss[r * APAD + tx * 4 + 0] = p0;
            Ss[r * APAD + tx * 4 + 1] = p1;
            Ss[r * APAD + tx * 4 + 2] = p2;
            Ss[r * APAD + tx * 4 + 3] = p3;
        }
        __syncthreads();

        // O += P V   (4 rows x 4 d-cols per thread, d paired)
        #pragma unroll 8
        for (int k = 0; k < 64; k++) {
            ull v0 = *(const ull*)&Vs[k * APAD + tx * 4];
            ull v1 = *(const ull*)&Vs[k * APAD + tx * 4 + 2];
            #pragma unroll
            for (int i = 0; i < 4; i++) {
                float p = Ss[(ty * 4 + i) * APAD + k];
                ull pp = pk2(p, p);
                FMA2(o2[i][0], pp, v0);
                FMA2(o2[i][1], pp, v1);
            }
        }
        __syncthreads();
    }

    // finalize: O /= l, stage into Ss[row][d], transpose-write [b,c,t]
    #pragma unroll
    for (int i = 0; i < 4; i++) {
        float inv = 1.0f / lrow[i];
        ull iv = pk2(inv, inv);
        MUL2(o2[i][0], iv);
        MUL2(o2[i][1], iv);
        float r0, r1, r2, r3;
        upk2(r0, r1, o2[i][0]);
        upk2(r2, r3, o2[i][1]);
        int r = ty * 4 + i;
        Ss[r * APAD + tx * 4 + 0] = r0;
        Ss[r * APAD + tx * 4 + 1] = r1;
        Ss[r * APAD + tx * 4 + 2] = r2;
        Ss[r * APAD + tx * 4 + 3] = r3;
    }
    __syncthreads();
    float* Og = g_ao + bh * (size_t)D * T;   // == b*C*T + (h*64)*T
    for (int i = tid; i < 64 * 64; i += 256) {
        int d = i >> 6, r = i & 63;
        Og[(size_t)d * T + t0 + r] = Ss[r * APAD + d];
    }
}

// =====================================================================
// Kernel 4: output projection.  out[b,o,t] = Wo[o,:] . g_ao[b,:,t] + bo[o]
// Same GEMM skeleton; 128 o x 128 t tiles, coalesced [b,c,t] writes.
// =====================================================================
__global__ __launch_bounds__(256) void out_gemm(
    const float* __restrict__ Wo, const float* __restrict__ bo,
    float* __restrict__ out)
{
    __shared__ float As[8][132];  // Wo^T tile [k][o]
    __shared__ float Bs[8][132];  // g_ao tile [k][t]

    const int b  = blockIdx.z;
    const int o0 = blockIdx.y * 128;
    const int t0 = blockIdx.x * 128;
    const float* Xb = g_ao + (size_t)b * C * T;

    const int tid = threadIdx.x;
    const int tx  = tid & 15, ty = tid >> 4;
    const int tm0 = ty * 8;          // o sub-tile
    const int tn0 = tx * 8;          // t sub-tile

    const int la_m = tid >> 1;            // 0..127 (o)
    const int la_k = (tid & 1) * 4;
    const int lb_k = tid >> 5;            // 0..7
    const int lb_n = (tid & 31) * 4;      // 0..124

    ull acc[8][4];
    #pragma unroll
    for (int i = 0; i < 8; i++)
        #pragma unroll
        for (int j = 0; j < 4; j++) acc[i][j] = 0ull;

    for (int kk = 0; kk < C; kk += 8) {
        float4 wv = *(const float4*)(Wo + (size_t)(o0 + la_m) * C + kk + la_k);
        float4 av = *(const float4*)(Xb + (size_t)(kk + lb_k) * T + t0 + lb_n);
        As[la_k + 0][la_m] = wv.x;
        As[la_k + 1][la_m] = wv.y;
        As[la_k + 2][la_m] = wv.z;
        As[la_k + 3][la_m] = wv.w;
        *(float4*)&Bs[lb_k][lb_n] = av;
        __syncthreads();
        #pragma unroll
        for (int k = 0; k < 8; k++) {
            float4 a0 = *(const float4*)&As[k][tm0];
            float4 a1 = *(const float4*)&As[k][tm0 + 4];
            const ull* bp = (const ull*)&Bs[k][tn0];
            ull bb0 = bp[0], bb1 = bp[1], bb2 = bp[2], bb3 = bp[3];
            float a[8] = {a0.x, a0.y, a0.z, a0.w, a1.x, a1.y, a1.z, a1.w};
            #pragma unroll
            for (int i = 0; i < 8; i++) {
                ull aa = pk2(a[i], a[i]);
                FMA2(acc[i][0], aa, bb0);
                FMA2(acc[i][1], aa, bb1);
                FMA2(acc[i][2], aa, bb2);
                FMA2(acc[i][3], aa, bb3);
            }
        }
        __syncthreads();
    }

    #pragma unroll
    for (int i = 0; i < 8; i++) {
        int o = o0 + tm0 + i;
        float bi = bo[o];
        float r[8];
        #pragma unroll
        for (int jp = 0; jp < 4; jp++) upk2(r[2 * jp], r[2 * jp + 1], acc[i][jp]);
        float4 s0 = make_float4(r[0] + bi, r[1] + bi, r[2] + bi, r[3] + bi);
        float4 s1 = make_float4(r[4] + bi, r[5] + bi, r[6] + bi, r[7] + bi);
        float* dst = out + (size_t)b * C * T + (size_t)o * T + t0 + tn0;
        *(float4*)(dst)     = s0;
        *(float4*)(dst + 4) = s1;
    }
}

// =====================================================================
extern "C" void kernel_launch(void* const* d_in, const int* in_sizes, int n_in,
                              void* d_out, int out_size)
{
    const float* x  = (const float*)d_in[0];
    const float* Wq = (const float*)d_in[1];
    const float* bq = (const float*)d_in[2];
    const float* Wk = (const float*)d_in[3];
    const float* bk = (const float*)d_in[4];
    const float* Wv = (const float*)d_in[5];
    const float* bv = (const float*)d_in[6];
    const float* Wo = (const float*)d_in[7];
    const float* bo = (const float*)d_in[8];
    float* out = (float*)d_out;

    const int attn_smem = 4 * 64 * APAD * (int)sizeof(float);   // 69632 B
    cudaFuncSetAttribute(attn_kernel,
                         cudaFuncAttributeMaxDynamicSharedMemorySize, attn_smem);

    qkv_gemm<<<dim3(T / 128, 12, B), 256>>>(x, Wq, bq, Wk, bk, Wv, bv);
    rope_kernel<<<(2 * B * H * T * 16) / 256, 256>>>();
    attn_kernel<<<dim3(T / 64, H, B), 256, attn_smem>>>();
    out_gemm<<<dim3(T / 128, C / 128, B), 256>>>(Wo, bo, out);
}

// round 7
// speedup vs baseline: 3.1543x; 3.1543x over previous
#include <cuda_runtime.h>
#include <math.h>

#define B   16
#define C   512
#define T   1024
#define H   8
#define D   64

// ---------------- scratch (static device, no allocation) ----------------
__device__ float  g_q [B*H*T*D];   // [b,h,t,d]
__device__ float  g_k [B*H*T*D];   // [b,h,t,d]
__device__ float  g_v [B*H*T*D];   // [b,h,t,d]
__device__ float  g_ao[B*C*T];     // [b,c,t]
__device__ float2 g_rope[T*16];    // {cos,sin} per (t, pair)

// ---------------- tf32 helpers ----------------
__device__ __forceinline__ unsigned tf32(float f) {
    unsigned r; asm("cvt.rna.tf32.f32 %0, %1;" : "=r"(r) : "f"(f)); return r;
}
__device__ __forceinline__ void mma_tf32(float* c, const unsigned* a, const unsigned* b) {
    asm volatile(
        "mma.sync.aligned.m16n8k8.row.col.f32.tf32.tf32.f32 "
        "{%0,%1,%2,%3}, {%4,%5,%6,%7}, {%8,%9}, {%0,%1,%2,%3};\n"
        : "+f"(c[0]), "+f"(c[1]), "+f"(c[2]), "+f"(c[3])
        : "r"(a[0]), "r"(a[1]), "r"(a[2]), "r"(a[3]), "r"(b[0]), "r"(b[1]));
}

// =====================================================================
// Kernel 1: QKV projection (tf32 tensor cores).
// out[b,o,t] = W[o,:].x[b,:,t] + bias[o], written as [b,h,t,d].
// Block tile 128(o) x 128(t), K-chunk 32. 8 warps, warp tile 32x64.
// =====================================================================
__global__ __launch_bounds__(256) void qkv_gemm_tc(
    const float* __restrict__ x,
    const float* __restrict__ Wq, const float* __restrict__ bq,
    const float* __restrict__ Wk, const float* __restrict__ bk,
    const float* __restrict__ Wv, const float* __restrict__ bv)
{
    __shared__ unsigned As[128*36];   // W tile  [o][k], stride 36
    __shared__ unsigned Bs[32*132];   // x tile  [k][t], stride 132

    const int b  = blockIdx.z;
    const int w  = blockIdx.y >> 2;          // 0=q 1=k 2=v
    const int o0 = (blockIdx.y & 3) * 128;
    const int t0 = blockIdx.x * 128;

    const float* W    = (w == 0) ? Wq : (w == 1) ? Wk : Wv;
    const float* bias = (w == 0) ? bq : (w == 1) ? bk : bv;
    float*       outb = (w == 0) ? g_q : (w == 1) ? g_k : g_v;
    const float* Xb   = x + (size_t)b * C * T;

    const int tid  = threadIdx.x;
    const int lane = tid & 31, warp = tid >> 5;
    const int gid  = lane >> 2, tg = lane & 3;
    const int m0   = (warp >> 1) * 32;
    const int n0   = (warp & 1) * 64;

    const int ar0 = tid >> 3, ac = (tid & 7) * 4;
    const int br0 = tid >> 5, bc = (tid & 31) * 4;

    float acc[2][8][4];
    #pragma unroll
    for (int mf = 0; mf < 2; mf++)
        #pragma unroll
        for (int nf = 0; nf < 8; nf++)
            #pragma unroll
            for (int i = 0; i < 4; i++) acc[mf][nf][i] = 0.0f;

    for (int kk = 0; kk < C; kk += 32) {
        #pragma unroll
        for (int i = 0; i < 4; i++) {
            int r = ar0 + i * 32;
            float4 wv = *(const float4*)(W + (size_t)(o0 + r) * C + kk + ac);
            unsigned* p = &As[r * 36 + ac];
            p[0] = tf32(wv.x); p[1] = tf32(wv.y); p[2] = tf32(wv.z); p[3] = tf32(wv.w);
        }
        #pragma unroll
        for (int i = 0; i < 4; i++) {
            int r = br0 + i * 8;
            float4 xv = *(const float4*)(Xb + (size_t)(kk + r) * T + t0 + bc);
            unsigned* p = &Bs[r * 132 + bc];
            p[0] = tf32(xv.x); p[1] = tf32(xv.y); p[2] = tf32(xv.z); p[3] = tf32(xv.w);
        }
        __syncthreads();
        #pragma unroll
        for (int k8 = 0; k8 < 4; k8++) {
            const int kb = k8 * 8;
            unsigned a[2][4], bf[8][2];
            #pragma unroll
            for (int mf = 0; mf < 2; mf++) {
                int r = m0 + mf * 16 + gid;
                a[mf][0] = As[r * 36 + kb + tg];
                a[mf][1] = As[(r + 8) * 36 + kb + tg];
                a[mf][2] = As[r * 36 + kb + tg + 4];
                a[mf][3] = As[(r + 8) * 36 + kb + tg + 4];
            }
            #pragma unroll
            for (int nf = 0; nf < 8; nf++) {
                int cn = n0 + nf * 8 + gid;
                bf[nf][0] = Bs[(kb + tg) * 132 + cn];
                bf[nf][1] = Bs[(kb + tg + 4) * 132 + cn];
            }
            #pragma unroll
            for (int mf = 0; mf < 2; mf++)
                #pragma unroll
                for (int nf = 0; nf < 8; nf++)
                    mma_tf32(acc[mf][nf], a[mf], bf[nf]);
        }
        __syncthreads();
    }

    // epilogue: bias + write [b,h,t,d]
    #pragma unroll
    for (int mf = 0; mf < 2; mf++) {
        int o1 = o0 + m0 + mf * 16 + gid;
        int o2 = o1 + 8;
        float bi1 = bias[o1], bi2 = bias[o2];
        float* p1 = outb + ((size_t)(b * H + (o1 >> 6)) * T) * D + (o1 & 63);
        float* p2 = outb + ((size_t)(b * H + (o2 >> 6)) * T) * D + (o2 & 63);
        #pragma unroll
        for (int nf = 0; nf < 8; nf++) {
            int t = t0 + n0 + nf * 8 + 2 * tg;
            p1[(size_t)t * D]       = acc[mf][nf][0] + bi1;
            p1[(size_t)(t + 1) * D] = acc[mf][nf][1] + bi1;
            p2[(size_t)t * D]       = acc[mf][nf][2] + bi2;
            p2[(size_t)(t + 1) * D] = acc[mf][nf][3] + bi2;
        }
    }
}

// =====================================================================
// Kernel 2a: RoPE table (fp64 once, tiny).  2b: apply (fp32, mem-bound).
// =====================================================================
__global__ void rope_table()
{
    const int idx = blockIdx.x * blockDim.x + threadIdx.x;  // 16384
    const int t = idx >> 4, i = idx & 15;
    double theta = exp(-(double)i * (9.210340371976184 / 16.0)); // ln(10000)/16
    double sd, cd;
    sincos((double)t * theta, &sd, &cd);
    g_rope[idx] = make_float2((float)cd, (float)sd);
}

__global__ __launch_bounds__(256) void rope_apply()
{
    const int idx = blockIdx.x * blockDim.x + threadIdx.x;  // 2*131072*4
    const int buf = idx >> 19;
    const int j   = idx & 524287;
    const int row = j >> 2;                 // [b,h,t] flattened
    const int qd  = j & 3;                  // pair quad 0..3
    const int t   = row & (T - 1);

    float* base = (buf ? g_k : g_q) + (size_t)row * D + qd * 4;
    float4 a  = *(const float4*)base;
    float4 bb = *(const float4*)(base + 16);
    const float4* tp = (const float4*)(g_rope + t * 16 + qd * 4);
    float4 t0v = tp[0], t1v = tp[1];   // {c0,s0,c1,s1},{c2,s2,c3,s3}

    float4 r0, r1;
    r0.x = a.x * t0v.x - bb.x * t0v.y;  r1.x = bb.x * t0v.x + a.x * t0v.y;
    r0.y = a.y * t0v.z - bb.y * t0v.w;  r1.y = bb.y * t0v.z + a.y * t0v.w;
    r0.z = a.z * t1v.x - bb.z * t1v.y;  r1.z = bb.z * t1v.x + a.z * t1v.y;
    r0.w = a.w * t1v.z - bb.w * t1v.w;  r1.w = bb.w * t1v.z + a.w * t1v.w;
    *(float4*)base        = r0;
    *(float4*)(base + 16) = r1;
}

// =====================================================================
// Kernel 3: flash attention, tf32 tensor cores.
// Block = (b, h, 64 q-rows); 4 warps, warp = 16 q-rows vs all 64 keys.
// Online softmax (quad shfl), P round-trips via smem as tf32.
// =====================================================================
#define ASTR 68

__global__ __launch_bounds__(128) void attn_tc()
{
    extern __shared__ unsigned sm_u[];
    unsigned* Qs = sm_u;              // [64][68] tf32, pre-scaled
    unsigned* Ks = Qs + 64 * ASTR;    // [64][68] tf32, [key][d]
    unsigned* Vs = Ks + 64 * ASTR;    // [64][68] tf32, [key][d]
    unsigned* Ss = Vs + 64 * ASTR;    // [64][68] P (tf32) / O staging (f32)
    float*    Sf = reinterpret_cast<float*>(Ss);

    const int b = blockIdx.z, h = blockIdx.y, t0 = blockIdx.x * 64;
    const size_t bh = (size_t)(b * H + h);
    const float* Qg = g_q + bh * T * D;
    const float* Kg = g_k + bh * T * D;
    const float* Vg = g_v + bh * T * D;

    const int tid = threadIdx.x, lane = tid & 31, warp = tid >> 5;
    const int gid = lane >> 2, tg = lane & 3;
    const int m0  = warp * 16;

    // load Q tile, pre-scaled by 1/8
    #pragma unroll
    for (int j = 0; j < 8; j++) {
        int u = tid + j * 128;
        int r = u >> 4, c4 = (u & 15) * 4;
        float4 qv = *(const float4*)(Qg + (size_t)(t0 + r) * D + c4);
        unsigned* p = &Qs[r * ASTR + c4];
        p[0] = tf32(0.125f * qv.x); p[1] = tf32(0.125f * qv.y);
        p[2] = tf32(0.125f * qv.z); p[3] = tf32(0.125f * qv.w);
    }

    float oacc[8][4];
    #pragma unroll
    for (int nf = 0; nf < 8; nf++)
        #pragma unroll
        for (int i = 0; i < 4; i++) oacc[nf][i] = 0.0f;
    float mr[2] = {-INFINITY, -INFINITY}, lr[2] = {0.0f, 0.0f};

    for (int kb = 0; kb < T / 64; kb++) {
        __syncthreads();                      // prev PV done before overwrite
        const int k0 = kb * 64;
        #pragma unroll
        for (int j = 0; j < 8; j++) {
            int u = tid + j * 128;
            int r = u >> 4, c4 = (u & 15) * 4;
            float4 kv = *(const float4*)(Kg + (size_t)(k0 + r) * D + c4);
            unsigned* p = &Ks[r * ASTR + c4];
            p[0] = tf32(kv.x); p[1] = tf32(kv.y); p[2] = tf32(kv.z); p[3] = tf32(kv.w);
            float4 vv = *(const float4*)(Vg + (size_t)(k0 + r) * D + c4);
            unsigned* q = &Vs[r * ASTR + c4];
            q[0] = tf32(vv.x); q[1] = tf32(vv.y); q[2] = tf32(vv.z); q[3] = tf32(vv.w);
        }
        __syncthreads();

        // S = Q K^T
        float sacc[8][4];
        #pragma unroll
        for (int nf = 0; nf < 8; nf++)
            #pragma unroll
            for (int i = 0; i < 4; i++) sacc[nf][i] = 0.0f;
        #pragma unroll
        for (int k8 = 0; k8 < 8; k8++) {
            const int kc = k8 * 8;
            unsigned a[4];
            a[0] = Qs[(m0 + gid) * ASTR + kc + tg];
            a[1] = Qs[(m0 + gid + 8) * ASTR + kc + tg];
            a[2] = Qs[(m0 + gid) * ASTR + kc + tg + 4];
            a[3] = Qs[(m0 + gid + 8) * ASTR + kc + tg + 4];
            #pragma unroll
            for (int nf = 0; nf < 8; nf++) {
                unsigned bb[2];
                bb[0] = Ks[(nf * 8 + gid) * ASTR + kc + tg];
                bb[1] = Ks[(nf * 8 + gid) * ASTR + kc + tg + 4];
                mma_tf32(sacc[nf], a, bb);
            }
        }

        // online softmax; rows: hf=0 -> m0+gid, hf=1 -> m0+gid+8
        #pragma unroll
        for (int hf = 0; hf < 2; hf++) {
            float mx = -INFINITY;
            #pragma unroll
            for (int nf = 0; nf < 8; nf++)
                mx = fmaxf(mx, fmaxf(sacc[nf][hf * 2], sacc[nf][hf * 2 + 1]));
            mx = fmaxf(mx, __shfl_xor_sync(0xffffffffu, mx, 1));
            mx = fmaxf(mx, __shfl_xor_sync(0xffffffffu, mx, 2));
            float mn = fmaxf(mr[hf], mx);
            float al = __expf(mr[hf] - mn);
            mr[hf] = mn;
            float sum = 0.0f;
            const int row = m0 + gid + hf * 8;
            #pragma unroll
            for (int nf = 0; nf < 8; nf++) {
                float p0 = __expf(sacc[nf][hf * 2] - mn);
                float p1 = __expf(sacc[nf][hf * 2 + 1] - mn);
                sum += p0 + p1;
                Ss[row * ASTR + nf * 8 + 2 * tg]     = tf32(p0);
                Ss[row * ASTR + nf * 8 + 2 * tg + 1] = tf32(p1);
                oacc[nf][hf * 2]     *= al;
                oacc[nf][hf * 2 + 1] *= al;
            }
            sum += __shfl_xor_sync(0xffffffffu, sum, 1);
            sum += __shfl_xor_sync(0xffffffffu, sum, 2);
            lr[hf] = lr[hf] * al + sum;
        }
        __syncthreads();

        // O += P V
        #pragma unroll
        for (int k8 = 0; k8 < 8; k8++) {
            const int kc = k8 * 8;
            unsigned a[4];
            a[0] = Ss[(m0 + gid) * ASTR + kc + tg];
            a[1] = Ss[(m0 + gid + 8) * ASTR + kc + tg];
            a[2] = Ss[(m0 + gid) * ASTR + kc + tg + 4];
            a[3] = Ss[(m0 + gid + 8) * ASTR + kc + tg + 4];
            #pragma unroll
            for (int nf = 0; nf < 8; nf++) {
                unsigned bb[2];
                bb[0] = Vs[(kc + tg) * ASTR + nf * 8 + gid];
                bb[1] = Vs[(kc + tg + 4) * ASTR + nf * 8 + gid];
                mma_tf32(oacc[nf], a, bb);
            }
        }
    }

    __syncthreads();
    // finalize, stage [row][d] in f32, transpose-write [b,c,t]
    const float inv0 = 1.0f / lr[0], inv1 = 1.0f / lr[1];
    #pragma unroll
    for (int nf = 0; nf < 8; nf++) {
        int cc = nf * 8 + 2 * tg;
        Sf[(m0 + gid) * ASTR + cc]         = oacc[nf][0] * inv0;
        Sf[(m0 + gid) * ASTR + cc + 1]     = oacc[nf][1] * inv0;
        Sf[(m0 + gid + 8) * ASTR + cc]     = oacc[nf][2] * inv1;
        Sf[(m0 + gid + 8) * ASTR + cc + 1] = oacc[nf][3] * inv1;
    }
    __syncthreads();
    float* Og = g_ao + bh * (size_t)D * T;
    #pragma unroll
    for (int j = 0; j < 32; j++) {
        int u = tid + j * 128;
        int dd = u >> 6, r = u & 63;
        Og[(size_t)dd * T + t0 + r] = Sf[r * ASTR + dd];
    }
}

// =====================================================================
// Kernel 4: output projection (tf32 tensor cores), [b,c,t] coalesced out.
// =====================================================================
__global__ __launch_bounds__(256) void out_gemm_tc(
    const float* __restrict__ Wo, const float* __restrict__ bo,
    float* __restrict__ out)
{
    __shared__ unsigned As[128*36];   // Wo tile [o][k]
    __shared__ unsigned Bs[32*132];   // ao tile [k][t]

    const int b  = blockIdx.z;
    const int o0 = blockIdx.y * 128;
    const int t0 = blockIdx.x * 128;
    const float* Xb = g_ao + (size_t)b * C * T;

    const int tid  = threadIdx.x;
    const int lane = tid & 31, warp = tid >> 5;
    const int gid  = lane >> 2, tg = lane & 3;
    const int m0   = (warp >> 1) * 32;
    const int n0   = (warp & 1) * 64;

    const int ar0 = tid >> 3, ac = (tid & 7) * 4;
    const int br0 = tid >> 5, bc = (tid & 31) * 4;

    float acc[2][8][4];
    #pragma unroll
    for (int mf = 0; mf < 2; mf++)
        #pragma unroll
        for (int nf = 0; nf < 8; nf++)
            #pragma unroll
            for (int i = 0; i < 4; i++) acc[mf][nf][i] = 0.0f;

    for (int kk = 0; kk < C; kk += 32) {
        #pragma unroll
        for (int i = 0; i < 4; i++) {
            int r = ar0 + i * 32;
            float4 wv = *(const float4*)(Wo + (size_t)(o0 + r) * C + kk + ac);
            unsigned* p = &As[r * 36 + ac];
            p[0] = tf32(wv.x); p[1] = tf32(wv.y); p[2] = tf32(wv.z); p[3] = tf32(wv.w);
        }
        #pragma unroll
        for (int i = 0; i < 4; i++) {
            int r = br0 + i * 8;
            float4 xv = *(const float4*)(Xb + (size_t)(kk + r) * T + t0 + bc);
            unsigned* p = &Bs[r * 132 + bc];
            p[0] = tf32(xv.x); p[1] = tf32(xv.y); p[2] = tf32(xv.z); p[3] = tf32(xv.w);
        }
        __syncthreads();
        #pragma unroll
        for (int k8 = 0; k8 < 4; k8++) {
            const int kb = k8 * 8;
            unsigned a[2][4], bf[8][2];
            #pragma unroll
            for (int mf = 0; mf < 2; mf++) {
                int r = m0 + mf * 16 + gid;
                a[mf][0] = As[r * 36 + kb + tg];
                a[mf][1] = As[(r + 8) * 36 + kb + tg];
                a[mf][2] = As[r * 36 + kb + tg + 4];
                a[mf][3] = As[(r + 8) * 36 + kb + tg + 4];
            }
            #pragma unroll
            for (int nf = 0; nf < 8; nf++) {
                int cn = n0 + nf * 8 + gid;
                bf[nf][0] = Bs[(kb + tg) * 132 + cn];
                bf[nf][1] = Bs[(kb + tg + 4) * 132 + cn];
            }
            #pragma unroll
            for (int mf = 0; mf < 2; mf++)
                #pragma unroll
                for (int nf = 0; nf < 8; nf++)
                    mma_tf32(acc[mf][nf], a[mf], bf[nf]);
        }
        __syncthreads();
    }

    #pragma unroll
    for (int mf = 0; mf < 2; mf++) {
        int o1 = o0 + m0 + mf * 16 + gid;
        int o2 = o1 + 8;
        float bi1 = bo[o1], bi2 = bo[o2];
        float* p1 = out + (size_t)b * C * T + (size_t)o1 * T;
        float* p2 = out + (size_t)b * C * T + (size_t)o2 * T;
        #pragma unroll
        for (int nf = 0; nf < 8; nf++) {
            int t = t0 + n0 + nf * 8 + 2 * tg;
            float2 v1 = make_float2(acc[mf][nf][0] + bi1, acc[mf][nf][1] + bi1);
            float2 v2 = make_float2(acc[mf][nf][2] + bi2, acc[mf][nf][3] + bi2);
            *(float2*)(p1 + t) = v1;
            *(float2*)(p2 + t) = v2;
        }
    }
}

// =====================================================================
extern "C" void kernel_launch(void* const* d_in, const int* in_sizes, int n_in,
                              void* d_out, int out_size)
{
    const float* x  = (const float*)d_in[0];
    const float* Wq = (const float*)d_in[1];
    const float* bq = (const float*)d_in[2];
    const float* Wk = (const float*)d_in[3];
    const float* bk = (const float*)d_in[4];
    const float* Wv = (const float*)d_in[5];
    const float* bv = (const float*)d_in[6];
    const float* Wo = (const float*)d_in[7];
    const float* bo = (const float*)d_in[8];
    float* out = (float*)d_out;

    const int attn_smem = 4 * 64 * ASTR * (int)sizeof(unsigned);   // 69632 B
    cudaFuncSetAttribute(attn_tc,
                         cudaFuncAttributeMaxDynamicSharedMemorySize, attn_smem);

    qkv_gemm_tc<<<dim3(T / 128, 12, B), 256>>>(x, Wq, bq, Wk, bk, Wv, bv);
    rope_table<<<64, 256>>>();
    rope_apply<<<(2 * B * H * T * 4) / 256, 256>>>();
    attn_tc<<<dim3(T / 64, H, B), 128, attn_smem>>>();
    out_gemm_tc<<<dim3(T / 128, C / 128, B), 256>>>(Wo, bo, out);
}

// round 8
// speedup vs baseline: 3.3906x; 1.0749x over previous
#include <cuda_runtime.h>
#include <math.h>

#define B   16
#define C   512
#define T   1024
#define H   8
#define D   64

// ---------------- scratch (static device, no allocation) ----------------
__device__ float  g_q [B*H*T*D];   // [b,h,t,d]
__device__ float  g_k [B*H*T*D];   // [b,h,t,d]
__device__ float  g_v [B*H*T*D];   // [b,h,t,d]
__device__ float  g_ao[B*C*T];     // [b,c,t]
__device__ float2 g_rope[T*16];    // {cos,sin} per (t, pair)

// ---------------- tf32 helpers ----------------
__device__ __forceinline__ unsigned tf32(float f) {
    unsigned r; asm("cvt.rna.tf32.f32 %0, %1;" : "=r"(r) : "f"(f)); return r;
}
__device__ __forceinline__ void mma_tf32(float* c, const unsigned* a, const unsigned* b) {
    asm volatile(
        "mma.sync.aligned.m16n8k8.row.col.f32.tf32.tf32.f32 "
        "{%0,%1,%2,%3}, {%4,%5,%6,%7}, {%8,%9}, {%0,%1,%2,%3};\n"
        : "+f"(c[0]), "+f"(c[1]), "+f"(c[2]), "+f"(c[3])
        : "r"(a[0]), "r"(a[1]), "r"(a[2]), "r"(a[3]), "r"(b[0]), "r"(b[1]));
}
// pair-interleave within 8-groups: (0,4)(1,5)(2,6)(3,7) -> adjacent slots
__device__ __forceinline__ int ilv(int d) {
    return (d & ~7) | (((d & 3) << 1) | ((d & 7) >> 2));
}

// =====================================================================
// Kernel 1: QKV projection (tf32 tensor cores).
// =====================================================================
__global__ __launch_bounds__(256) void qkv_gemm_tc(
    const float* __restrict__ x,
    const float* __restrict__ Wq, const float* __restrict__ bq,
    const float* __restrict__ Wk, const float* __restrict__ bk,
    const float* __restrict__ Wv, const float* __restrict__ bv)
{
    __shared__ unsigned As[128*36];   // W tile  [o][k], stride 36
    __shared__ unsigned Bs[32*132];   // x tile  [k][t], stride 132

    const int b  = blockIdx.z;
    const int w  = blockIdx.y >> 2;          // 0=q 1=k 2=v
    const int o0 = (blockIdx.y & 3) * 128;
    const int t0 = blockIdx.x * 128;

    const float* W    = (w == 0) ? Wq : (w == 1) ? Wk : Wv;
    const float* bias = (w == 0) ? bq : (w == 1) ? bk : bv;
    float*       outb = (w == 0) ? g_q : (w == 1) ? g_k : g_v;
    const float* Xb   = x + (size_t)b * C * T;

    const int tid  = threadIdx.x;
    const int lane = tid & 31, warp = tid >> 5;
    const int gid  = lane >> 2, tg = lane & 3;
    const int m0   = (warp >> 1) * 32;
    const int n0   = (warp & 1) * 64;

    const int ar0 = tid >> 3, ac = (tid & 7) * 4;
    const int br0 = tid >> 5, bc = (tid & 31) * 4;

    float acc[2][8][4];
    #pragma unroll
    for (int mf = 0; mf < 2; mf++)
        #pragma unroll
        for (int nf = 0; nf < 8; nf++)
            #pragma unroll
            for (int i = 0; i < 4; i++) acc[mf][nf][i] = 0.0f;

    for (int kk = 0; kk < C; kk += 32) {
        #pragma unroll
        for (int i = 0; i < 4; i++) {
            int r = ar0 + i * 32;
            float4 wv = *(const float4*)(W + (size_t)(o0 + r) * C + kk + ac);
            unsigned* p = &As[r * 36 + ac];
            p[0] = tf32(wv.x); p[1] = tf32(wv.y); p[2] = tf32(wv.z); p[3] = tf32(wv.w);
        }
        #pragma unroll
        for (int i = 0; i < 4; i++) {
            int r = br0 + i * 8;
            float4 xv = *(const float4*)(Xb + (size_t)(kk + r) * T + t0 + bc);
            unsigned* p = &Bs[r * 132 + bc];
            p[0] = tf32(xv.x); p[1] = tf32(xv.y); p[2] = tf32(xv.z); p[3] = tf32(xv.w);
        }
        __syncthreads();
        #pragma unroll
        for (int k8 = 0; k8 < 4; k8++) {
            const int kb = k8 * 8;
            unsigned a[2][4], bf[8][2];
            #pragma unroll
            for (int mf = 0; mf < 2; mf++) {
                int r = m0 + mf * 16 + gid;
                a[mf][0] = As[r * 36 + kb + tg];
                a[mf][1] = As[(r + 8) * 36 + kb + tg];
                a[mf][2] = As[r * 36 + kb + tg + 4];
                a[mf][3] = As[(r + 8) * 36 + kb + tg + 4];
            }
            #pragma unroll
            for (int nf = 0; nf < 8; nf++) {
                int cn = n0 + nf * 8 + gid;
                bf[nf][0] = Bs[(kb + tg) * 132 + cn];
                bf[nf][1] = Bs[(kb + tg + 4) * 132 + cn];
            }
            #pragma unroll
            for (int mf = 0; mf < 2; mf++)
                #pragma unroll
                for (int nf = 0; nf < 8; nf++)
                    mma_tf32(acc[mf][nf], a[mf], bf[nf]);
        }
        __syncthreads();
    }

    #pragma unroll
    for (int mf = 0; mf < 2; mf++) {
        int o1 = o0 + m0 + mf * 16 + gid;
        int o2 = o1 + 8;
        float bi1 = bias[o1], bi2 = bias[o2];
        float* p1 = outb + ((size_t)(b * H + (o1 >> 6)) * T) * D + (o1 & 63);
        float* p2 = outb + ((size_t)(b * H + (o2 >> 6)) * T) * D + (o2 & 63);
        #pragma unroll
        for (int nf = 0; nf < 8; nf++) {
            int t = t0 + n0 + nf * 8 + 2 * tg;
            p1[(size_t)t * D]       = acc[mf][nf][0] + bi1;
            p1[(size_t)(t + 1) * D] = acc[mf][nf][1] + bi1;
            p2[(size_t)t * D]       = acc[mf][nf][2] + bi2;
            p2[(size_t)(t + 1) * D] = acc[mf][nf][3] + bi2;
        }
    }
}

// =====================================================================
// Kernel 2a: RoPE table (fp64 once, tiny).  2b: apply (fp32, mem-bound).
// =====================================================================
__global__ void rope_table()
{
    const int idx = blockIdx.x * blockDim.x + threadIdx.x;  // 16384
    const int t = idx >> 4, i = idx & 15;
    double theta = exp(-(double)i * (9.210340371976184 / 16.0)); // ln(10000)/16
    double sd, cd;
    sincos((double)t * theta, &sd, &cd);
    g_rope[idx] = make_float2((float)cd, (float)sd);
}

__global__ __launch_bounds__(256) void rope_apply()
{
    const int idx = blockIdx.x * blockDim.x + threadIdx.x;  // 2*131072*4
    const int buf = idx >> 19;
    const int j   = idx & 524287;
    const int row = j >> 2;                 // [b,h,t] flattened
    const int qd  = j & 3;                  // pair quad 0..3
    const int t   = row & (T - 1);

    float* base = (buf ? g_k : g_q) + (size_t)row * D + qd * 4;
    float4 a  = *(const float4*)base;
    float4 bb = *(const float4*)(base + 16);
    const float4* tp = (const float4*)(g_rope + t * 16 + qd * 4);
    float4 t0v = tp[0], t1v = tp[1];   // {c0,s0,c1,s1},{c2,s2,c3,s3}

    float4 r0, r1;
    r0.x = a.x * t0v.x - bb.x * t0v.y;  r1.x = bb.x * t0v.x + a.x * t0v.y;
    r0.y = a.y * t0v.z - bb.y * t0v.w;  r1.y = bb.y * t0v.z + a.y * t0v.w;
    r0.z = a.z * t1v.x - bb.z * t1v.y;  r1.z = bb.z * t1v.x + a.z * t1v.y;
    r0.w = a.w * t1v.z - bb.w * t1v.w;  r1.w = bb.w * t1v.z + a.w * t1v.w;
    *(float4*)base        = r0;
    *(float4*)(base + 16) = r1;
}

// =====================================================================
// Kernel 3: flash attention v2 (tf32 tensor cores).
// Block = (b, h, 128 q-rows); 8 warps, warp = 16 q-rows vs 64-key tiles.
// Pair-interleaved smem -> all fragment loads are LDS.64.
// P stays in registers (shfl permutation), no smem round-trip.
// =====================================================================
#define QSTR 72

__global__ __launch_bounds__(256, 2) void attn_tc2()
{
    extern __shared__ unsigned sm_u[];
    unsigned* Qs = sm_u;               // [128][72] tf32, pre-scaled, d interleaved
    unsigned* Ks = Qs + 128 * QSTR;    // [64 key][72] tf32, d interleaved
    unsigned* Vt = Ks + 64 * QSTR;     // [64 d][72] tf32, key interleaved (transposed)
    float*    Sf = reinterpret_cast<float*>(Ks);  // epilogue staging [128][65]

    const int b = blockIdx.z, h = blockIdx.y, t0 = blockIdx.x * 128;
    const size_t bh = (size_t)(b * H + h);
    const float* Qg = g_q + bh * T * D;
    const float* Kg = g_k + bh * T * D;
    const float* Vg = g_v + bh * T * D;

    const int tid = threadIdx.x, lane = tid & 31, warp = tid >> 5;
    const int gid = lane >> 2, tg = lane & 3;
    const int m0  = warp * 16;

    // ---- load Q tile (pre-scaled by 1/8, interleaved) ----
    #pragma unroll
    for (int j = 0; j < 8; j++) {
        int u = tid + j * 256;
        int r = u >> 4, c4 = (u & 15) << 2;
        float4 qv = *(const float4*)(Qg + (size_t)(t0 + r) * D + c4);
        unsigned* p = &Qs[r * QSTR];
        p[ilv(c4 + 0)] = tf32(0.125f * qv.x);
        p[ilv(c4 + 1)] = tf32(0.125f * qv.y);
        p[ilv(c4 + 2)] = tf32(0.125f * qv.z);
        p[ilv(c4 + 3)] = tf32(0.125f * qv.w);
    }

    float oacc[8][4];
    #pragma unroll
    for (int nf = 0; nf < 8; nf++)
        #pragma unroll
        for (int i = 0; i < 4; i++) oacc[nf][i] = 0.0f;
    float mr[2] = {-INFINITY, -INFINITY}, lr[2] = {0.0f, 0.0f};

    for (int kb = 0; kb < T / 64; kb++) {
        const int k0 = kb * 64;
        // ---- prefetch K/V tile into registers (overlaps peers' compute) ----
        float4 kr[4], vr[4];
        #pragma unroll
        for (int j = 0; j < 4; j++) {
            int u = tid + j * 256;
            kr[j] = *(const float4*)(Kg + (size_t)(k0 + (u >> 4)) * D + ((u & 15) << 2));
            vr[j] = *(const float4*)(Vg + (size_t)(k0 + (u & 63)) * D + ((u >> 6) << 2));
        }
        __syncthreads();   // everyone done with previous tile
        #pragma unroll
        for (int j = 0; j < 4; j++) {
            int u = tid + j * 256;
            int r = u >> 4, c4 = (u & 15) << 2;
            unsigned* p = &Ks[r * QSTR];
            p[ilv(c4 + 0)] = tf32(kr[j].x);
            p[ilv(c4 + 1)] = tf32(kr[j].y);
            p[ilv(c4 + 2)] = tf32(kr[j].z);
            p[ilv(c4 + 3)] = tf32(kr[j].w);
            int rv = u & 63, cv = (u >> 6) << 2;
            int cr = ilv(rv);
            Vt[(cv + 0) * QSTR + cr] = tf32(vr[j].x);
            Vt[(cv + 1) * QSTR + cr] = tf32(vr[j].y);
            Vt[(cv + 2) * QSTR + cr] = tf32(vr[j].z);
            Vt[(cv + 3) * QSTR + cr] = tf32(vr[j].w);
        }
        __syncthreads();

        // ---- S = Q K^T ----
        float sacc[8][4];
        #pragma unroll
        for (int nf = 0; nf < 8; nf++)
            #pragma unroll
            for (int i = 0; i < 4; i++) sacc[nf][i] = 0.0f;
        #pragma unroll
        for (int k8 = 0; k8 < 8; k8++) {
            const int kc = k8 * 8 + 2 * tg;
            uint2 qa0 = *(const uint2*)&Qs[(m0 + gid) * QSTR + kc];
            uint2 qa1 = *(const uint2*)&Qs[(m0 + gid + 8) * QSTR + kc];
            unsigned a[4] = {qa0.x, qa1.x, qa0.y, qa1.y};
            #pragma unroll
            for (int nf = 0; nf < 8; nf++) {
                uint2 kbv = *(const uint2*)&Ks[(nf * 8 + gid) * QSTR + kc];
                unsigned bbv[2] = {kbv.x, kbv.y};
                mma_tf32(sacc[nf], a, bbv);
            }
        }

        // ---- online softmax (quad reductions), exp in place ----
        #pragma unroll
        for (int hf = 0; hf < 2; hf++) {
            float mx = -INFINITY;
            #pragma unroll
            for (int nf = 0; nf < 8; nf++)
                mx = fmaxf(mx, fmaxf(sacc[nf][hf * 2], sacc[nf][hf * 2 + 1]));
            mx = fmaxf(mx, __shfl_xor_sync(0xffffffffu, mx, 1));
            mx = fmaxf(mx, __shfl_xor_sync(0xffffffffu, mx, 2));
            float mn = fmaxf(mr[hf], mx);
            float al = __expf(mr[hf] - mn);
            mr[hf] = mn;
            float sum = 0.0f;
            #pragma unroll
            for (int nf = 0; nf < 8; nf++) {
                float p0 = __expf(sacc[nf][hf * 2] - mn);
                float p1 = __expf(sacc[nf][hf * 2 + 1] - mn);
                sacc[nf][hf * 2]     = p0;
                sacc[nf][hf * 2 + 1] = p1;
                sum += p0 + p1;
                oacc[nf][hf * 2]     *= al;
                oacc[nf][hf * 2 + 1] *= al;
            }
            sum += __shfl_xor_sync(0xffffffffu, sum, 1);
            sum += __shfl_xor_sync(0xffffffffu, sum, 2);
            lr[hf] = lr[hf] * al + sum;
        }

        // ---- O += P V  (P permuted accumulator->A via quad shfl) ----
        const int sl0 = (lane & ~3) | (tg >> 1);
        const bool od = (tg & 1);
        #pragma unroll
        for (int k8 = 0; k8 < 8; k8++) {
            float v00 = __shfl_sync(0xffffffffu, sacc[k8][0], sl0);
            float v01 = __shfl_sync(0xffffffffu, sacc[k8][1], sl0);
            float v10 = __shfl_sync(0xffffffffu, sacc[k8][2], sl0);
            float v11 = __shfl_sync(0xffffffffu, sacc[k8][3], sl0);
            float v20 = __shfl_sync(0xffffffffu, sacc[k8][0], sl0 + 2);
            float v21 = __shfl_sync(0xffffffffu, sacc[k8][1], sl0 + 2);
            float v30 = __shfl_sync(0xffffffffu, sacc[k8][2], sl0 + 2);
            float v31 = __shfl_sync(0xffffffffu, sacc[k8][3], sl0 + 2);
            unsigned pa[4];
            pa[0] = tf32(od ? v01 : v00);
            pa[1] = tf32(od ? v11 : v10);
            pa[2] = tf32(od ? v21 : v20);
            pa[3] = tf32(od ? v31 : v30);
            const int kc = k8 * 8 + 2 * tg;
            #pragma unroll
            for (int nf = 0; nf < 8; nf++) {
                uint2 vb = *(const uint2*)&Vt[(nf * 8 + gid) * QSTR + kc];
                unsigned bbv[2] = {vb.x, vb.y};
                mma_tf32(oacc[nf], pa, bbv);
            }
        }
    }

    // ---- epilogue: normalize, stage (stride 65: conflict-free transpose read) ----
    __syncthreads();
    const float inv0 = 1.0f / lr[0], inv1 = 1.0f / lr[1];
    #pragma unroll
    for (int nf = 0; nf < 8; nf++) {
        int cc = nf * 8 + 2 * tg;
        Sf[(m0 + gid) * 65 + cc]         = oacc[nf][0] * inv0;
        Sf[(m0 + gid) * 65 + cc + 1]     = oacc[nf][1] * inv0;
        Sf[(m0 + gid + 8) * 65 + cc]     = oacc[nf][2] * inv1;
        Sf[(m0 + gid + 8) * 65 + cc + 1] = oacc[nf][3] * inv1;
    }
    __syncthreads();
    float* Og = g_ao + bh * (size_t)D * T;
    #pragma unroll
    for (int j = 0; j < 32; j++) {
        int u = tid + j * 256;
        int dd = u >> 7, r = u & 127;
        Og[(size_t)dd * T + t0 + r] = Sf[r * 65 + dd];
    }
}

// =====================================================================
// Kernel 4: output projection (tf32 tensor cores), [b,c,t] coalesced out.
// =====================================================================
__global__ __launch_bounds__(256) void out_gemm_tc(
    const float* __restrict__ Wo, const float* __restrict__ bo,
    float* __restrict__ out)
{
    __shared__ unsigned As[128*36];   // Wo tile [o][k]
    __shared__ unsigned Bs[32*132];   // ao tile [k][t]

    const int b  = blockIdx.z;
    const int o0 = blockIdx.y * 128;
    const int t0 = blockIdx.x * 128;
    const float* Xb = g_ao + (size_t)b * C * T;

    const int tid  = threadIdx.x;
    const int lane = tid & 31, warp = tid >> 5;
    const int gid  = lane >> 2, tg = lane & 3;
    const int m0   = (warp >> 1) * 32;
    const int n0   = (warp & 1) * 64;

    const int ar0 = tid >> 3, ac = (tid & 7) * 4;
    const int br0 = tid >> 5, bc = (tid & 31) * 4;

    float acc[2][8][4];
    #pragma unroll
    for (int mf = 0; mf < 2; mf++)
        #pragma unroll
        for (int nf = 0; nf < 8; nf++)
            #pragma unroll
            for (int i = 0; i < 4; i++) acc[mf][nf][i] = 0.0f;

    for (int kk = 0; kk < C; kk += 32) {
        #pragma unroll
        for (int i = 0; i < 4; i++) {
            int r = ar0 + i * 32;
            float4 wv = *(const float4*)(Wo + (size_t)(o0 + r) * C + kk + ac);
            unsigned* p = &As[r * 36 + ac];
            p[0] = tf32(wv.x); p[1] = tf32(wv.y); p[2] = tf32(wv.z); p[3] = tf32(wv.w);
        }
        #pragma unroll
        for (int i = 0; i < 4; i++) {
            int r = br0 + i * 8;
            float4 xv = *(const float4*)(Xb + (size_t)(kk + r) * T + t0 + bc);
            unsigned* p = &Bs[r * 132 + bc];
            p[0] = tf32(xv.x); p[1] = tf32(xv.y); p[2] = tf32(xv.z); p[3] = tf32(xv.w);
        }
        __syncthreads();
        #pragma unroll
        for (int k8 = 0; k8 < 4; k8++) {
            const int kb = k8 * 8;
            unsigned a[2][4], bf[8][2];
            #pragma unroll
            for (int mf = 0; mf < 2; mf++) {
                int r = m0 + mf * 16 + gid;
                a[mf][0] = As[r * 36 + kb + tg];
                a[mf][1] = As[(r + 8) * 36 + kb + tg];
                a[mf][2] = As[r * 36 + kb + tg + 4];
                a[mf][3] = As[(r + 8) * 36 + kb + tg + 4];
            }
            #pragma unroll
            for (int nf = 0; nf < 8; nf++) {
                int cn = n0 + nf * 8 + gid;
                bf[nf][0] = Bs[(kb + tg) * 132 + cn];
                bf[nf][1] = Bs[(kb + tg + 4) * 132 + cn];
            }
            #pragma unroll
            for (int mf = 0; mf < 2; mf++)
                #pragma unroll
                for (int nf = 0; nf < 8; nf++)
                    mma_tf32(acc[mf][nf], a[mf], bf[nf]);
        }
        __syncthreads();
    }

    #pragma unroll
    for (int mf = 0; mf < 2; mf++) {
        int o1 = o0 + m0 + mf * 16 + gid;
        int o2 = o1 + 8;
        float bi1 = bo[o1], bi2 = bo[o2];
        float* p1 = out + (size_t)b * C * T + (size_t)o1 * T;
        float* p2 = out + (size_t)b * C * T + (size_t)o2 * T;
        #pragma unroll
        for (int nf = 0; nf < 8; nf++) {
            int t = t0 + n0 + nf * 8 + 2 * tg;
            float2 v1 = make_float2(acc[mf][nf][0] + bi1, acc[mf][nf][1] + bi1);
            float2 v2 = make_float2(acc[mf][nf][2] + bi2, acc[mf][nf][3] + bi2);
            *(float2*)(p1 + t) = v1;
            *(float2*)(p2 + t) = v2;
        }
    }
}

// =====================================================================
extern "C" void kernel_launch(void* const* d_in, const int* in_sizes, int n_in,
                              void* d_out, int out_size)
{
    const float* x  = (const float*)d_in[0];
    const float* Wq = (const float*)d_in[1];
    const float* bq = (const float*)d_in[2];
    const float* Wk = (const float*)d_in[3];
    const float* bk = (const float*)d_in[4];
    const float* Wv = (const float*)d_in[5];
    const float* bv = (const float*)d_in[6];
    const float* Wo = (const float*)d_in[7];
    const float* bo = (const float*)d_in[8];
    float* out = (float*)d_out;

    const int attn_smem = (128 + 64 + 64) * QSTR * (int)sizeof(unsigned); // 73728 B
    cudaFuncSetAttribute(attn_tc2,
                         cudaFuncAttributeMaxDynamicSharedMemorySize, attn_smem);

    qkv_gemm_tc<<<dim3(T / 128, 12, B), 256>>>(x, Wq, bq, Wk, bk, Wv, bv);
    rope_table<<<64, 256>>>();
    rope_apply<<<(2 * B * H * T * 4) / 256, 256>>>();
    attn_tc2<<<dim3(T / 128, H, B), 256, attn_smem>>>();
    out_gemm_tc<<<dim3(T / 128, C / 128, B), 256>>>(Wo, bo, out);
}